// round 11
// baseline (speedup 1.0000x reference)
#include <cuda_runtime.h>

// out[b, i] = x[b, i] * diagonal[i]
// x: [8192, 4096] f32, diagonal: [4096] f32, out: [8192, 4096] f32
//
// FINAL (confirming R9, the measured best: 35.26us kernel, 6031 GB/s,
// DRAM 76.2%). Block-size sweep verdict: 256->36.0us, 512->35.26us (best),
// 1024->36.29us. All other axes (vector width, MLP, cache hints, wave
// structure, diag handling) measured neutral or worse — this sits at the
// effective GB300 mixed 1:1 R/W HBM ceiling for a 256MiB streaming op.
//
// Layout: each thread owns ONE float4 column and 4 consecutive rows.
//  - diagonal loaded once per thread (no per-element diag loads)
//  - 4 front-batched independent streaming loads (MLP=4)
//  - evict-streaming hints on both read-once and write-once streams
//  - 28 regs, THREADS=512, 4096 blocks

static constexpr int SIZE     = 4096;
static constexpr int BATCH    = 8192;
static constexpr int SIZE_V4  = SIZE / 4;              // 1024 float4 per row
static constexpr int THREADS  = 512;
static constexpr int COL_CHUNKS = SIZE_V4 / THREADS;   // 2
static constexpr int ROWS_PER_THREAD = 4;
static constexpr int ROW_BLOCKS = BATCH / ROWS_PER_THREAD;  // 2048

__global__ __launch_bounds__(THREADS)
void diag_scale_kernel(const float4* __restrict__ x,
                       const float4* __restrict__ diag,
                       float4* __restrict__ out)
{
    // blockIdx.x = row_block * COL_CHUNKS + col_chunk
    const int col_chunk = blockIdx.x & (COL_CHUNKS - 1);
    const int row_block = blockIdx.x >> 1;            // / COL_CHUNKS

    const int c = col_chunk * THREADS + threadIdx.x;  // float4 column
    const float4 dv = __ldg(&diag[c]);                // ONE diag load per thread

    const long long base =
        (long long)row_block * ROWS_PER_THREAD * SIZE_V4 + c;

    // Front-batched independent loads: MLP = 4
    float4 xv[ROWS_PER_THREAD];
#pragma unroll
    for (int k = 0; k < ROWS_PER_THREAD; k++)
        xv[k] = __ldcs(&x[base + (long long)k * SIZE_V4]);

#pragma unroll
    for (int k = 0; k < ROWS_PER_THREAD; k++) {
        float4 ov;
        ov.x = xv[k].x * dv.x;
        ov.y = xv[k].y * dv.y;
        ov.z = xv[k].z * dv.z;
        ov.w = xv[k].w * dv.w;
        __stcs(&out[base + (long long)k * SIZE_V4], ov);
    }
}

extern "C" void kernel_launch(void* const* d_in, const int* in_sizes, int n_in,
                              void* d_out, int out_size)
{
    const float4* x    = (const float4*)d_in[0];
    const float4* diag = (const float4*)d_in[1];
    float4*       out  = (float4*)d_out;

    const int blocks = ROW_BLOCKS * COL_CHUNKS;   // 4096
    diag_scale_kernel<<<blocks, THREADS>>>(x, diag, out);
}

// round 12
// speedup vs baseline: 1.0228x; 1.0228x over previous
#include <cuda_runtime.h>

// out[b, i] = x[b, i] * diagonal[i]
// x: [8192, 4096] f32, diagonal: [4096] f32, out: [8192, 4096] f32
//
// FINAL — measured optimum, reproduced twice (R9: 35.26us/6031GB/s,
// R11: 35.58us/5983GB/s). Sits at the effective GB300 mixed 1:1 R/W HBM
// ceiling (~75% of 8TB/s spec) with issue<8% and all compute pipes <4%.
// Full axis sweep verdict (11 rounds): block=512 optimal (256/1024 worse);
// MLP=4 optimal (8 regresses via registers); 128b ≡ 256b accesses;
// cs ≡ wt ≡ default hints; multi-wave ≡ persistent grid.
//
// Layout: each thread owns ONE float4 column and 4 consecutive rows.
//  - diagonal loaded once per thread (no per-element diag loads)
//  - 4 front-batched independent streaming loads (MLP=4)
//  - evict-streaming hints on both read-once and write-once streams
//  - 28 regs, THREADS=512, 4096 blocks

static constexpr int SIZE     = 4096;
static constexpr int BATCH    = 8192;
static constexpr int SIZE_V4  = SIZE / 4;              // 1024 float4 per row
static constexpr int THREADS  = 512;
static constexpr int COL_CHUNKS = SIZE_V4 / THREADS;   // 2
static constexpr int ROWS_PER_THREAD = 4;
static constexpr int ROW_BLOCKS = BATCH / ROWS_PER_THREAD;  // 2048

__global__ __launch_bounds__(THREADS)
void diag_scale_kernel(const float4* __restrict__ x,
                       const float4* __restrict__ diag,
                       float4* __restrict__ out)
{
    // blockIdx.x = row_block * COL_CHUNKS + col_chunk
    const int col_chunk = blockIdx.x & (COL_CHUNKS - 1);
    const int row_block = blockIdx.x >> 1;            // / COL_CHUNKS

    const int c = col_chunk * THREADS + threadIdx.x;  // float4 column
    const float4 dv = __ldg(&diag[c]);                // ONE diag load per thread

    const long long base =
        (long long)row_block * ROWS_PER_THREAD * SIZE_V4 + c;

    // Front-batched independent loads: MLP = 4
    float4 xv[ROWS_PER_THREAD];
#pragma unroll
    for (int k = 0; k < ROWS_PER_THREAD; k++)
        xv[k] = __ldcs(&x[base + (long long)k * SIZE_V4]);

#pragma unroll
    for (int k = 0; k < ROWS_PER_THREAD; k++) {
        float4 ov;
        ov.x = xv[k].x * dv.x;
        ov.y = xv[k].y * dv.y;
        ov.z = xv[k].z * dv.z;
        ov.w = xv[k].w * dv.w;
        __stcs(&out[base + (long long)k * SIZE_V4], ov);
    }
}

extern "C" void kernel_launch(void* const* d_in, const int* in_sizes, int n_in,
                              void* d_out, int out_size)
{
    const float4* x    = (const float4*)d_in[0];
    const float4* diag = (const float4*)d_in[1];
    float4*       out  = (float4*)d_out;

    const int blocks = ROW_BLOCKS * COL_CHUNKS;   // 4096
    diag_scale_kernel<<<blocks, THREADS>>>(x, diag, out);
}